// round 14
// baseline (speedup 1.0000x reference)
#include <cuda_runtime.h>
#include <cuda_bf16.h>
#include <math.h>
#include <stdint.h>

#define BB 2048
#define DD 256
#define CC 512
#define NROW 8192
#define INVTAU (1.0f/0.07f)
#define WTOT 720896    // 256*(1024+1024+512+256)

// ---------------- scratch (no allocations allowed) ----------------
__device__ __nv_bfloat16 g_whi[WTOT], g_wlo[WTOT];
__device__ __nv_bfloat16 g_Zhi[NROW * DD], g_Zlo[NROW * DD];
__device__ __nv_bfloat16 g_Bhi[1024 * DD], g_Blo[1024 * DD]; // interleaved rows: 2c=Un_c, 2c+1=O_c
__device__ float         g_rnorm[NROW];

#define MMA_BF16(d, a, b) asm volatile( \
    "mma.sync.aligned.m16n8k16.row.col.f32.bf16.bf16.f32 " \
    "{%0,%1,%2,%3}, {%4,%5,%6,%7}, {%8,%9}, {%0,%1,%2,%3};\n" \
    : "+f"((d)[0]), "+f"((d)[1]), "+f"((d)[2]), "+f"((d)[3]) \
    : "r"((a)[0]), "r"((a)[1]), "r"((a)[2]), "r"((a)[3]), "r"((b)[0]), "r"((b)[1]))

#define LDM4(r, addr) asm volatile( \
    "ldmatrix.sync.aligned.m8n8.x4.shared.b16 {%0,%1,%2,%3}, [%4];" \
    : "=r"((r)[0]), "=r"((r)[1]), "=r"((r)[2]), "=r"((r)[3]) : "r"(addr))

#define CP16(dst, src) asm volatile("cp.async.cg.shared.global [%0], [%1], 16;" :: "r"(dst), "l"(src))
#define CP_COMMIT()    asm volatile("cp.async.commit_group;" ::: "memory")
#define CP_WAIT0()     asm volatile("cp.async.wait_group 0;" ::: "memory")
#define CP_WAIT1()     asm volatile("cp.async.wait_group 1;" ::: "memory")

__device__ __forceinline__ uint32_t smem_u32(const void* p) {
    uint32_t a;
    asm("{ .reg .u64 t; cvta.to.shared.u64 t, %1; cvt.u32.u64 %0, t; }" : "=r"(a) : "l"(p));
    return a;
}
__device__ __forceinline__ void split2(float x, __nv_bfloat16& h, __nv_bfloat16& l) {
    h = __float2bfloat16_rn(x);
    l = __float2bfloat16_rn(x - __bfloat162float(h));
}
__device__ __forceinline__ uint32_t pack2(__nv_bfloat16 a, __nv_bfloat16 b) {
    __nv_bfloat162 t = __halves2bfloat162(a, b);
    return *(uint32_t*)&t;
}
// split float2 -> packed bf16x2 hi + lo (same rounding as split2)
__device__ __forceinline__ void splitf2(float2 v, uint32_t& hi, uint32_t& lo) {
    __nv_bfloat16 h0, l0, h1, l1;
    split2(v.x, h0, l0); split2(v.y, h1, l1);
    hi = pack2(h0, h1); lo = pack2(l0, l1);
}

// smem layout header:
//  [0]     params: bias|gamma|beta (768 f)          3072 B
//  [3072]  smred: 4 warp-cols x ROWS x 2           <=2048 B
//  [5120]  stats: ROWS x 2 (mu,rstd)                <=512 B
//  [5632]  tiles: 2 stages
//  stage (!AFP32): Ahi 0 | Alo A_ARR | Bhi 2*A_ARR | Blo 2*A_ARR+B_ARR
//  stage (AFP32):  Bhi 0 | Blo B_ARR               (80 B/row)
#define SM_PARAM 0
#define SM_RED   3072
#define SM_STAT  5120
#define SM_T     5632
#define SMEM_PROJ (SM_T + 2 * (2 * 256 * 80))                 // 87552 (A via LDG)
#define SMEM_HEAD (SM_T + 2 * (2 * 64 * 80 + 2 * 128 * 80))   // 67072

// issue cp.async for one K32 stage (256 thr)
template<int NIM, int NCOL, bool AFP32>
__device__ __forceinline__ void load_stage_async(
    uint32_t tile_sm, const __nv_bfloat16* Ah, const __nv_bfloat16* Al,
    const __nv_bfloat16* Bh, const __nv_bfloat16* Bl,
    int lda, int ldb, int k0, int tid)
{
    constexpr int ROWS   = 32 * NIM;
    constexpr int A_ARR  = ROWS * 80;
    constexpr int B_ARR  = NCOL * 80;
    constexpr int B_BASE = AFP32 ? 0 : 2 * A_ARR;
    if (!AFP32) {
#pragma unroll
        for (int i = 0; i < NIM; i++) {   // A: 2 arrays x ROWS*4 uint4
            const int n = tid + (i << 8);
            const int a = n / (ROWS * 4), idx = n % (ROWS * 4);
            const int row = idx >> 2, ch = idx & 3;
            const __nv_bfloat16* src = a ? Al : Ah;
            const char* gsrc = (const char*)(src + (long)row * lda + k0 + (ch << 3));
            CP16(tile_sm + a * A_ARR + row * 80 + (ch << 4), gsrc);
        }
    }
#pragma unroll
    for (int i = 0; i < NCOL / 32; i++) {   // B: 2 arrays x NCOL*4 uint4
        const int m = tid + (i << 8);
        const int a = m / (NCOL * 4), idx = m % (NCOL * 4);
        const int row = idx >> 2, ch = idx & 3;
        const __nv_bfloat16* src = a ? Bl : Bh;
        const char* gsrc = (const char*)(src + (long)row * ldb + k0 + (ch << 3));
        CP16(tile_sm + B_BASE + a * B_ARR + row * 80 + (ch << 4), gsrc);
    }
    CP_COMMIT();
}

// LDG fp32 A fragments for one K32 stage (AFP32 path, NIM==1).
// fA[s*4+j]: s = k16 step, j: row g+8*(j&1), k += 8*(j>>1).
__device__ __forceinline__ void ldg_a_stage(
    const float* Arow, int lda, int k0, int t4, float2 fA[8])
{
#pragma unroll
    for (int s = 0; s < 2; s++)
#pragma unroll
        for (int j = 0; j < 4; j++) {
            const int r8 = (j & 1) * 8;
            const int k = k0 + 16 * s + 2 * t4 + 8 * (j >> 1);
            fA[s * 4 + j] = *(const float2*)(Arow + (long)r8 * lda + k);
        }
}

// ---------------------------------------------------------------------------
// CTA tile (32*NIM) rows x NCOL cols, 256 threads, warp grid 2x4.
//   proj: <1,256,2,true>  mode 0, grid (1, 64, 4)  — A direct from fp32 f
//   head: <2,128,3,false> mode 1, grid (8, 128, 1) — unchanged round-13 config
// ---------------------------------------------------------------------------
template<int NIM, int NCOL, int MINB, bool AFP32>
__global__ void __launch_bounds__(256, MINB) gemm_fused(
    int mode,
    const float* fp0, const float* fp1, const float* fp2, const float* fp3,
    const float* b0, const float* b1, const float* b2, const float* b3,
    const float* G0, const float* G1, const float* G2, const float* G3,
    const float* e0, const float* e1, const float* e2, const float* e3,
    const float* cls, float* out_logits, float* out_r,
    float* out_sim, float* out_contrib)
{
    constexpr int ROWS    = 32 * NIM;
    constexpr int A_ARR   = ROWS * 80;
    constexpr int B_ARR   = NCOL * 80;
    constexpr int B_BASE  = AFP32 ? 0 : 2 * A_ARR;
    constexpr int STAGE_B = B_BASE + 2 * B_ARR;
    constexpr int NJJ     = NCOL / 64;
    constexpr int WCOL    = NCOL / 4;

    extern __shared__ char smem[];
    const uint32_t sbase = smem_u32(smem);
    const int tid = threadIdx.x, wid = tid >> 5, lane = tid & 31;
    float* smf   = (float*)(smem + SM_PARAM);
    float* smred = (float*)(smem + SM_RED);
    float* smst  = (float*)(smem + SM_STAT);

    const int md = (mode == 0) ? blockIdx.z : 0;
    if (mode == 0) {
        const float* bp = md == 0 ? b0 : md == 1 ? b1 : md == 2 ? b2 : b3;
        const float* gp = md == 0 ? G0 : md == 1 ? G1 : md == 2 ? G2 : G3;
        const float* ep = md == 0 ? e0 : md == 1 ? e1 : md == 2 ? e2 : e3;
        smf[tid] = bp[tid]; smf[256 + tid] = gp[tid]; smf[512 + tid] = ep[tid];
    }
    __syncthreads();

    const int wm = wid >> 2, wn = wid & 3;    // 2x4 warp grid
    const int g = lane >> 2, t4 = lane & 3;

    // operand pointers
    const __nv_bfloat16 *Ah = nullptr, *Al = nullptr, *Bh, *Bl;
    const float* Afrow = nullptr;   // AFP32: fp32 A row base for this thread
    int lda, ldb, K;
    const int row0 = blockIdx.y * ROWS;
    if (mode == 0) {
        const int Km[4] = {1024, 1024, 512, 256};
        const long woff[4] = {0, 262144, 524288, 655360};
        K = Km[md];
        const float* fsrc = md == 0 ? fp0 : md == 1 ? fp1 : md == 2 ? fp2 : fp3;
        Afrow = fsrc + (long)(row0 + wm * 16 + g) * K;
        Bh = g_whi + woff[md];
        Bl = g_wlo + woff[md];
        lda = ldb = K;
    } else {
        K = DD;
        Ah = g_Zhi + (long)row0 * DD;
        Al = g_Zlo + (long)row0 * DD;
        Bh = g_Bhi + (long)blockIdx.x * NCOL * DD;
        Bl = g_Blo + (long)blockIdx.x * NCOL * DD;
        lda = ldb = DD;
    }
    const int nkt = K >> 5;

    uint32_t aoff[NIM];
#pragma unroll
    for (int im = 0; im < NIM; im++)
        aoff[im] = ((wm * (16 * NIM) + im * 16 + (lane & 15)) * 40
                    + ((lane >> 4) << 3)) * 2;
    const uint32_t boff = ((wn * WCOL + (lane & 7) + ((lane >> 4) << 3)) * 40
                           + (((lane >> 3) & 1) << 3)) * 2;

    float acc[NIM][2 * NJJ][4];
#pragma unroll
    for (int im = 0; im < NIM; im++)
#pragma unroll
        for (int jn = 0; jn < 2 * NJJ; jn++)
#pragma unroll
            for (int q = 0; q < 4; q++) acc[im][jn][q] = 0.f;

    float2 fA[2][8];

    // ---------------- cp.async double-buffered mainloop ----------------
    load_stage_async<NIM, NCOL, AFP32>(sbase + SM_T, Ah, Al, Bh, Bl, lda, ldb, 0, tid);
    if (AFP32) ldg_a_stage(Afrow, lda, 0, t4, fA[0]);
    for (int kt = 0; kt < nkt; kt++) {
        const bool hasNext = (kt + 1 < nkt);
        if (hasNext) {
            load_stage_async<NIM, NCOL, AFP32>(sbase + SM_T + ((kt + 1) & 1) * STAGE_B,
                                               Ah, Al, Bh, Bl, lda, ldb, (kt + 1) << 5, tid);
            if (AFP32) ldg_a_stage(Afrow, lda, (kt + 1) << 5, t4, fA[(kt + 1) & 1]);
        }
        if (hasNext) CP_WAIT1(); else CP_WAIT0();
        __syncthreads();

        const uint32_t sst = sbase + SM_T + (kt & 1) * STAGE_B;
#pragma unroll
        for (int ks = 0; ks < 64; ks += 32) {   // one k16 step = 32 B
            uint32_t ah[NIM][4], al[NIM][4];
            if (AFP32) {
#pragma unroll
                for (int j = 0; j < 4; j++)
                    splitf2(fA[kt & 1][(ks >> 5) * 4 + j], ah[0][j], al[0][j]);
            } else {
#pragma unroll
                for (int im = 0; im < NIM; im++) {
                    LDM4(ah[im], sst + aoff[im] + ks);
                    LDM4(al[im], sst + A_ARR + aoff[im] + ks);
                }
            }
#pragma unroll
            for (int jj = 0; jj < NJJ; jj++) {
                uint32_t bh[4], bl[4];
                LDM4(bh, sst + B_BASE + boff + jj * 1280 + ks);
                LDM4(bl, sst + B_BASE + B_ARR + boff + jj * 1280 + ks);
#pragma unroll
                for (int im = 0; im < NIM; im++) {
                    MMA_BF16(acc[im][2 * jj],     ah[im], &bh[0]);
                    MMA_BF16(acc[im][2 * jj],     ah[im], &bl[0]);
                    MMA_BF16(acc[im][2 * jj],     al[im], &bh[0]);
                    MMA_BF16(acc[im][2 * jj + 1], ah[im], &bh[2]);
                    MMA_BF16(acc[im][2 * jj + 1], ah[im], &bl[2]);
                    MMA_BF16(acc[im][2 * jj + 1], al[im], &bh[2]);
                }
            }
        }
        __syncthreads();
    }

    // ---------------- fused register epilogue ----------------
    // thread rows: wm*(16*NIM) + im*16 + g + 8h   cols: wn*WCOL + jn*8 + 2*t4 + e
    if (mode == 0) {
        float sums[NIM][2], ssqs[NIM][2];
#pragma unroll
        for (int im = 0; im < NIM; im++)
#pragma unroll
            for (int h = 0; h < 2; h++) { sums[im][h] = 0.f; ssqs[im][h] = 0.f; }
#pragma unroll
        for (int im = 0; im < NIM; im++)
#pragma unroll
            for (int jn = 0; jn < 2 * NJJ; jn++)
#pragma unroll
                for (int h = 0; h < 2; h++)
#pragma unroll
                    for (int e = 0; e < 2; e++) {
                        const int col = wn * WCOL + jn * 8 + 2 * t4 + e;
                        const float y = acc[im][jn][h * 2 + e] + smf[col];
                        acc[im][jn][h * 2 + e] = y;
                        sums[im][h] += y; ssqs[im][h] += y * y;
                    }
#pragma unroll
        for (int im = 0; im < NIM; im++)
#pragma unroll
            for (int h = 0; h < 2; h++) {
                sums[im][h] += __shfl_xor_sync(0xffffffffu, sums[im][h], 1);
                sums[im][h] += __shfl_xor_sync(0xffffffffu, sums[im][h], 2);
                ssqs[im][h] += __shfl_xor_sync(0xffffffffu, ssqs[im][h], 1);
                ssqs[im][h] += __shfl_xor_sync(0xffffffffu, ssqs[im][h], 2);
            }
        if (t4 == 0) {
#pragma unroll
            for (int im = 0; im < NIM; im++)
#pragma unroll
                for (int h = 0; h < 2; h++) {
                    const int row = wm * (16 * NIM) + im * 16 + g + 8 * h;
                    smred[wn * (ROWS * 2) + row * 2]     = sums[im][h];
                    smred[wn * (ROWS * 2) + row * 2 + 1] = ssqs[im][h];
                }
        }
        __syncthreads();
        if (tid < ROWS) {
            float s = 0.f, q = 0.f;
#pragma unroll
            for (int w = 0; w < 4; w++) {
                s += smred[w * (ROWS * 2) + tid * 2];
                q += smred[w * (ROWS * 2) + tid * 2 + 1];
            }
            const float mu = s * (1.f / 256.f);
            const float var = q * (1.f / 256.f) - mu * mu;
            smst[tid * 2]     = mu;
            smst[tid * 2 + 1] = rsqrtf(var + 1e-5f);
        }
        __syncthreads();

        float z2[NIM][2];
#pragma unroll
        for (int im = 0; im < NIM; im++)
#pragma unroll
            for (int h = 0; h < 2; h++) z2[im][h] = 0.f;
#pragma unroll
        for (int im = 0; im < NIM; im++)
#pragma unroll
            for (int h = 0; h < 2; h++) {
                const int row = wm * (16 * NIM) + im * 16 + g + 8 * h;
                const float mu = smst[row * 2], rstd = smst[row * 2 + 1];
                const long zrow = ((long)(row0 + row) * 4 + md) * 256;
#pragma unroll
                for (int jn = 0; jn < 2 * NJJ; jn++) {
                    const int c0 = wn * WCOL + jn * 8 + 2 * t4;
                    const float z0 = (acc[im][jn][h * 2]     - mu) * rstd * smf[256 + c0]     + smf[512 + c0];
                    const float z1 = (acc[im][jn][h * 2 + 1] - mu) * rstd * smf[256 + c0 + 1] + smf[512 + c0 + 1];
                    z2[im][h] += z0 * z0 + z1 * z1;
                    __nv_bfloat16 h0, l0, h1, l1;
                    split2(z0, h0, l0); split2(z1, h1, l1);
                    *(uint32_t*)(g_Zhi + zrow + c0) = pack2(h0, h1);
                    *(uint32_t*)(g_Zlo + zrow + c0) = pack2(l0, l1);
                }
            }
#pragma unroll
        for (int im = 0; im < NIM; im++)
#pragma unroll
            for (int h = 0; h < 2; h++) {
                z2[im][h] += __shfl_xor_sync(0xffffffffu, z2[im][h], 1);
                z2[im][h] += __shfl_xor_sync(0xffffffffu, z2[im][h], 2);
            }
        __syncthreads();
        if (t4 == 0) {
#pragma unroll
            for (int im = 0; im < NIM; im++)
#pragma unroll
                for (int h = 0; h < 2; h++) {
                    const int row = wm * (16 * NIM) + im * 16 + g + 8 * h;
                    smred[wn * (ROWS * 2) + row * 2] = z2[im][h];
                }
        }
        __syncthreads();
        if (tid < ROWS) {
            float n2 = 0.f;
#pragma unroll
            for (int w = 0; w < 4; w++) n2 += smred[w * (ROWS * 2) + tid * 2];
            g_rnorm[((long)(row0 + tid) * 4 + md)] = 1.f / (sqrtf(n2) + 1e-6f);
        }
    } else {
        // head: col pair (even,odd) = (Z.Un_cg, Z.O_cg); softmax over m via
        // shfl xor 4,8 (modality m = g&3 lives in lane bits 2..3).
#pragma unroll
        for (int im = 0; im < NIM; im++)
#pragma unroll
            for (int h = 0; h < 2; h++) {
                const long grow = row0 + wm * (16 * NIM) + im * 16 + g + 8 * h;
                const float rs = g_rnorm[grow] * INVTAU;
#pragma unroll
                for (int jn = 0; jn < 2 * NJJ; jn++) {
                    const float s = acc[im][jn][h * 2] * rs;
                    const float o = acc[im][jn][h * 2 + 1];
                    float mx = s;
                    mx = fmaxf(mx, __shfl_xor_sync(0xffffffffu, mx, 4));
                    mx = fmaxf(mx, __shfl_xor_sync(0xffffffffu, mx, 8));
                    const float e = __expf(s - mx);
                    float tt = e + __shfl_xor_sync(0xffffffffu, e, 4);
                    tt += __shfl_xor_sync(0xffffffffu, tt, 8);
                    const float rr = e / tt;
                    const float ct = o * rr;
                    float lg = ct + __shfl_xor_sync(0xffffffffu, ct, 4);
                    lg += __shfl_xor_sync(0xffffffffu, lg, 8);
                    const int cg = blockIdx.x * (NCOL / 2) + wn * (NCOL / 8) + jn * 4 + t4;
                    const long obase = grow * 512 + cg;
                    out_sim[obase]     = s;
                    out_r[obase]       = rr;
                    out_contrib[obase] = ct;
                    if ((grow & 3) == 0)
                        out_logits[(grow >> 2) * 512 + cg] = lg + __ldg(cls + cg);
                }
            }
    }
}

// ---------------------------------------------------------------------------
// fp32 -> bf16 hi/lo conversion for W_* only (f is consumed directly now)
// ---------------------------------------------------------------------------
__global__ void __launch_bounds__(256) cvt_w(
    const float* w0, const float* w1, const float* w2, const float* w3)
{
    const int cum[4] = {256, 512, 640, 704};
    int blk = blockIdx.x, seg = 0;
    while (blk >= cum[seg]) seg++;
    int lb = blk - (seg ? cum[seg - 1] : 0);
    const float* src;
    __nv_bfloat16 *hi, *lo;
    switch (seg) {
        case 0: src = w0; hi = g_whi;           lo = g_wlo;           break;
        case 1: src = w1; hi = g_whi + 262144;  lo = g_wlo + 262144;  break;
        case 2: src = w2; hi = g_whi + 524288;  lo = g_wlo + 524288;  break;
        default:src = w3; hi = g_whi + 655360;  lo = g_wlo + 655360;  break;
    }
    long base = (long)lb * 1024 + threadIdx.x * 4;
    float4 v = *(const float4*)(src + base);
    __nv_bfloat16 h0, h1, h2, h3, l0, l1, l2, l3;
    split2(v.x, h0, l0); split2(v.y, h1, l1);
    split2(v.z, h2, l2); split2(v.w, h3, l3);
    *(__nv_bfloat162*)(hi + base)     = __halves2bfloat162(h0, h1);
    *(__nv_bfloat162*)(hi + base + 2) = __halves2bfloat162(h2, h3);
    *(__nv_bfloat162*)(lo + base)     = __halves2bfloat162(l0, l1);
    *(__nv_bfloat162*)(lo + base + 2) = __halves2bfloat162(l2, l3);
}

// ---------------------------------------------------------------------------
// Bcat rows interleaved: row 2c = l2norm(U)_c, row 2c+1 = O_c  -> bf16 hi/lo
// ---------------------------------------------------------------------------
__global__ void __launch_bounds__(256) normcat_kernel(const float* __restrict__ U,
                                                      const float* __restrict__ O)
{
    const int rr = blockIdx.x, t = threadIdx.x;
    const int c = rr >> 1, kind = rr & 1;
    __shared__ float ws[8];
    float v;
    if (kind == 0) {
        float u = U[(long)c * DD + t];
        float q = u * u;
#pragma unroll
        for (int o = 16; o > 0; o >>= 1) q += __shfl_xor_sync(0xffffffffu, q, o);
        if ((t & 31) == 0) ws[t >> 5] = q;
        __syncthreads();
        float n2 = 0.f;
#pragma unroll
        for (int i = 0; i < 8; i++) n2 += ws[i];
        v = u / (sqrtf(n2) + 1e-6f);
    } else {
        v = O[(long)c * DD + t];
    }
    __nv_bfloat16 h, l; split2(v, h, l);
    g_Bhi[(long)rr * DD + t] = h;
    g_Blo[(long)rr * DD + t] = l;
}

// ---------------------------------------------------------------------------
extern "C" void kernel_launch(void* const* d_in, const int* in_sizes, int n_in,
                              void* d_out, int out_size)
{
    const float *f[4], *W[4], *bi[4], *ga[4], *be[4];
    if (in_sizes[1] == 256 * 1024) {   // dict order: (f,W,b,g,be) per modality
        for (int m = 0; m < 4; m++) {
            f[m]  = (const float*)d_in[m * 5 + 0];
            W[m]  = (const float*)d_in[m * 5 + 1];
            bi[m] = (const float*)d_in[m * 5 + 2];
            ga[m] = (const float*)d_in[m * 5 + 3];
            be[m] = (const float*)d_in[m * 5 + 4];
        }
    } else {                            // signature order
        for (int m = 0; m < 4; m++) f[m] = (const float*)d_in[m];
        for (int m = 0; m < 4; m++) {
            W[m]  = (const float*)d_in[4 + m * 4 + 0];
            bi[m] = (const float*)d_in[4 + m * 4 + 1];
            ga[m] = (const float*)d_in[4 + m * 4 + 2];
            be[m] = (const float*)d_in[4 + m * 4 + 3];
        }
    }
    const float* U   = (const float*)d_in[20];
    const float* O   = (const float*)d_in[21];
    const float* cls = (const float*)d_in[22];

    float* out         = (float*)d_out;
    float* out_logits  = out;
    float* out_r       = out + (long)BB * CC;
    float* out_sim     = out_r + (long)NROW * CC;
    float* out_contrib = out_sim + (long)NROW * CC;

    cudaFuncSetAttribute((const void*)gemm_fused<1, 256, 2, true>,
                         cudaFuncAttributeMaxDynamicSharedMemorySize, SMEM_PROJ);
    cudaFuncSetAttribute((const void*)gemm_fused<2, 128, 3, false>,
                         cudaFuncAttributeMaxDynamicSharedMemorySize, SMEM_HEAD);

    cvt_w<<<704, 256>>>(W[0], W[1], W[2], W[3]);
    normcat_kernel<<<1024, 256>>>(U, O);

    // projections + fused LayerNorm/l2: A loaded directly from fp32 f
    gemm_fused<1, 256, 2, true><<<dim3(1, 64, 4), 256, SMEM_PROJ>>>(
        0, f[0], f[1], f[2], f[3],
        bi[0], bi[1], bi[2], bi[3], ga[0], ga[1], ga[2], ga[3],
        be[0], be[1], be[2], be[3], nullptr, nullptr, nullptr, nullptr, nullptr);

    // head GEMM + fused softmax/finalize: unchanged round-13 config (control)
    gemm_fused<2, 128, 3, false><<<dim3(8, 128, 1), 256, SMEM_HEAD>>>(
        1, nullptr, nullptr, nullptr, nullptr,
        nullptr, nullptr, nullptr, nullptr, nullptr, nullptr, nullptr, nullptr,
        nullptr, nullptr, nullptr, nullptr, cls, out_logits, out_r, out_sim, out_contrib);
}

// round 15
// speedup vs baseline: 1.3894x; 1.3894x over previous
#include <cuda_runtime.h>
#include <cuda_bf16.h>
#include <math.h>
#include <stdint.h>

#define BB 2048
#define DD 256
#define CC 512
#define NROW 8192
#define INVTAU (1.0f/0.07f)

// ---------------- scratch (no allocations allowed) ----------------
__device__ __nv_bfloat16 g_Zhi[NROW * DD], g_Zlo[NROW * DD];
__device__ __nv_bfloat16 g_Bhi[1024 * DD], g_Blo[1024 * DD]; // interleaved rows: 2c=Un_c, 2c+1=O_c
__device__ float         g_rnorm[NROW];

#define MMA_BF16(d, a, b) asm volatile( \
    "mma.sync.aligned.m16n8k16.row.col.f32.bf16.bf16.f32 " \
    "{%0,%1,%2,%3}, {%4,%5,%6,%7}, {%8,%9}, {%0,%1,%2,%3};\n" \
    : "+f"((d)[0]), "+f"((d)[1]), "+f"((d)[2]), "+f"((d)[3]) \
    : "r"((a)[0]), "r"((a)[1]), "r"((a)[2]), "r"((a)[3]), "r"((b)[0]), "r"((b)[1]))

#define MMA_TF32(d, a, b) asm volatile( \
    "mma.sync.aligned.m16n8k8.row.col.f32.tf32.tf32.f32 " \
    "{%0,%1,%2,%3}, {%4,%5,%6,%7}, {%8,%9}, {%0,%1,%2,%3};\n" \
    : "+f"((d)[0]), "+f"((d)[1]), "+f"((d)[2]), "+f"((d)[3]) \
    : "r"((a)[0]), "r"((a)[1]), "r"((a)[2]), "r"((a)[3]), "r"((b)[0]), "r"((b)[1]))

#define CVT_TF32(o, x) asm("cvt.rna.tf32.f32 %0, %1;" : "=r"(o) : "f"(x))

#define LDM4(r, addr) asm volatile( \
    "ldmatrix.sync.aligned.m8n8.x4.shared.b16 {%0,%1,%2,%3}, [%4];" \
    : "=r"((r)[0]), "=r"((r)[1]), "=r"((r)[2]), "=r"((r)[3]) : "r"(addr))

#define CP16(dst, src) asm volatile("cp.async.cg.shared.global [%0], [%1], 16;" :: "r"(dst), "l"(src))
#define CP_COMMIT()    asm volatile("cp.async.commit_group;" ::: "memory")
#define CP_WAIT0()     asm volatile("cp.async.wait_group 0;" ::: "memory")
#define CP_WAIT1()     asm volatile("cp.async.wait_group 1;" ::: "memory")

__device__ __forceinline__ uint32_t smem_u32(const void* p) {
    uint32_t a;
    asm("{ .reg .u64 t; cvta.to.shared.u64 t, %1; cvt.u32.u64 %0, t; }" : "=r"(a) : "l"(p));
    return a;
}
__device__ __forceinline__ void split2(float x, __nv_bfloat16& h, __nv_bfloat16& l) {
    h = __float2bfloat16_rn(x);
    l = __float2bfloat16_rn(x - __bfloat162float(h));
}
__device__ __forceinline__ uint32_t pack2(__nv_bfloat16 a, __nv_bfloat16 b) {
    __nv_bfloat162 t = __halves2bfloat162(a, b);
    return *(uint32_t*)&t;
}

// common smem header
#define SM_PARAM 0
#define SM_RED   3072
#define SM_STAT  5120
#define SM_T     5632
// proj (tf32): stage = A 32x144 + B 256x144 = 41472
#define PSTAGE   41472
#define SMEM_PROJ (SM_T + 2 * PSTAGE)                         // 88576
// head (bf16 hi/lo): stage = 2*64*80 + 2*128*80 = 30720
#define SMEM_HEAD (SM_T + 2 * (2 * 64 * 80 + 2 * 128 * 80))   // 67072

// ===========================================================================
// PROJ: tf32 GEMM, CTA tile 32 rows x 256 cols, grid (1, 64, 4), 2 CTAs/SM.
// A = f (fp32), B = W (fp32), both cp.async'd raw. Fused LayerNorm + l2.
// ===========================================================================
__global__ void __launch_bounds__(256, 2) proj_tf32(
    const float* fp0, const float* fp1, const float* fp2, const float* fp3,
    const float* W0, const float* W1, const float* W2, const float* W3,
    const float* b0, const float* b1, const float* b2, const float* b3,
    const float* G0, const float* G1, const float* G2, const float* G3,
    const float* e0, const float* e1, const float* e2, const float* e3)
{
    extern __shared__ char smem[];
    const uint32_t sbase = smem_u32(smem);
    const int tid = threadIdx.x, wid = tid >> 5, lane = tid & 31;
    float* smf   = (float*)(smem + SM_PARAM);
    float* smred = (float*)(smem + SM_RED);
    float* smst  = (float*)(smem + SM_STAT);

    const int md = blockIdx.z;
    {
        const float* bp = md == 0 ? b0 : md == 1 ? b1 : md == 2 ? b2 : b3;
        const float* gp = md == 0 ? G0 : md == 1 ? G1 : md == 2 ? G2 : G3;
        const float* ep = md == 0 ? e0 : md == 1 ? e1 : md == 2 ? e2 : e3;
        smf[tid] = bp[tid]; smf[256 + tid] = gp[tid]; smf[512 + tid] = ep[tid];
    }
    __syncthreads();

    const int Km[4] = {1024, 1024, 512, 256};
    const int K = Km[md];
    const float* F = md == 0 ? fp0 : md == 1 ? fp1 : md == 2 ? fp2 : fp3;
    const float* W = md == 0 ? W0 : md == 1 ? W1 : md == 2 ? W2 : W3;
    const int row0 = blockIdx.y * 32;
    const int nkt = K >> 5;

    const int wm = wid >> 2, wn = wid & 3;    // 2x4 warp grid, warp tile 16x64
    const int g = lane >> 2, t4 = lane & 3;

    float acc[8][4];
#pragma unroll
    for (int jn = 0; jn < 8; jn++)
#pragma unroll
        for (int q = 0; q < 4; q++) acc[jn][q] = 0.f;

    // cp.async one K32 stage: A 32 rows x 128B, B 256 rows x 128B (144B stride)
    auto load_stage = [&](uint32_t tile_sm, int k0) {
        {
            const int row = tid >> 3, ch = tid & 7;   // 256 uint4
            CP16(tile_sm + row * 144 + (ch << 4),
                 (const char*)(F + (long)(row0 + row) * K + k0 + (ch << 2)));
        }
#pragma unroll
        for (int i = 0; i < 8; i++) {                 // 2048 uint4
            const int m = tid + (i << 8);
            const int row = m >> 3, ch = m & 7;
            CP16(tile_sm + 4608 + row * 144 + (ch << 4),
                 (const char*)(W + (long)row * K + k0 + (ch << 2)));
        }
        CP_COMMIT();
    };

    load_stage(sbase + SM_T, 0);
    for (int kt = 0; kt < nkt; kt++) {
        const bool hasNext = (kt + 1 < nkt);
        if (hasNext) load_stage(sbase + SM_T + ((kt + 1) & 1) * PSTAGE, (kt + 1) << 5);
        if (hasNext) CP_WAIT1(); else CP_WAIT0();
        __syncthreads();

        const float* smA = (const float*)(smem + SM_T + (kt & 1) * PSTAGE);
        const float* smB = smA + 1152;   // 32*36 floats
        const float* A0 = smA + (wm * 16 + g) * 36 + t4;
#pragma unroll
        for (int s = 0; s < 4; s++) {    // four k8 steps
            uint32_t a[4];
            CVT_TF32(a[0], A0[s * 8]);
            CVT_TF32(a[1], A0[8 * 36 + s * 8]);
            CVT_TF32(a[2], A0[s * 8 + 4]);
            CVT_TF32(a[3], A0[8 * 36 + s * 8 + 4]);
#pragma unroll
            for (int jn = 0; jn < 8; jn++) {
                const int n = wn * 64 + jn * 8 + g;
                uint32_t b[2];
                CVT_TF32(b[0], smB[n * 36 + s * 8 + t4]);
                CVT_TF32(b[1], smB[n * 36 + s * 8 + t4 + 4]);
                MMA_TF32(acc[jn], a, b);
            }
        }
        __syncthreads();
    }

    // ---- fused LayerNorm + l2 epilogue (rows: wm*16+g+8h, cols: wn*64+jn*8+2t4+e)
    float sums[2] = {0.f, 0.f}, ssqs[2] = {0.f, 0.f};
#pragma unroll
    for (int jn = 0; jn < 8; jn++)
#pragma unroll
        for (int h = 0; h < 2; h++)
#pragma unroll
            for (int e = 0; e < 2; e++) {
                const int col = wn * 64 + jn * 8 + 2 * t4 + e;
                const float y = acc[jn][h * 2 + e] + smf[col];
                acc[jn][h * 2 + e] = y;
                sums[h] += y; ssqs[h] += y * y;
            }
#pragma unroll
    for (int h = 0; h < 2; h++) {
        sums[h] += __shfl_xor_sync(0xffffffffu, sums[h], 1);
        sums[h] += __shfl_xor_sync(0xffffffffu, sums[h], 2);
        ssqs[h] += __shfl_xor_sync(0xffffffffu, ssqs[h], 1);
        ssqs[h] += __shfl_xor_sync(0xffffffffu, ssqs[h], 2);
    }
    if (t4 == 0) {
#pragma unroll
        for (int h = 0; h < 2; h++) {
            const int row = wm * 16 + g + 8 * h;
            smred[wn * 64 + row * 2]     = sums[h];
            smred[wn * 64 + row * 2 + 1] = ssqs[h];
        }
    }
    __syncthreads();
    if (tid < 32) {
        float s = 0.f, q = 0.f;
#pragma unroll
        for (int w = 0; w < 4; w++) {
            s += smred[w * 64 + tid * 2];
            q += smred[w * 64 + tid * 2 + 1];
        }
        const float mu = s * (1.f / 256.f);
        const float var = q * (1.f / 256.f) - mu * mu;
        smst[tid * 2]     = mu;
        smst[tid * 2 + 1] = rsqrtf(var + 1e-5f);
    }
    __syncthreads();

    float z2[2] = {0.f, 0.f};
#pragma unroll
    for (int h = 0; h < 2; h++) {
        const int row = wm * 16 + g + 8 * h;
        const float mu = smst[row * 2], rstd = smst[row * 2 + 1];
        const long zrow = ((long)(row0 + row) * 4 + md) * 256;
#pragma unroll
        for (int jn = 0; jn < 8; jn++) {
            const int c0 = wn * 64 + jn * 8 + 2 * t4;
            const float z0 = (acc[jn][h * 2]     - mu) * rstd * smf[256 + c0]     + smf[512 + c0];
            const float z1 = (acc[jn][h * 2 + 1] - mu) * rstd * smf[256 + c0 + 1] + smf[512 + c0 + 1];
            z2[h] += z0 * z0 + z1 * z1;
            __nv_bfloat16 h0, l0, h1, l1;
            split2(z0, h0, l0); split2(z1, h1, l1);
            *(uint32_t*)(g_Zhi + zrow + c0) = pack2(h0, h1);
            *(uint32_t*)(g_Zlo + zrow + c0) = pack2(l0, l1);
        }
    }
#pragma unroll
    for (int h = 0; h < 2; h++) {
        z2[h] += __shfl_xor_sync(0xffffffffu, z2[h], 1);
        z2[h] += __shfl_xor_sync(0xffffffffu, z2[h], 2);
    }
    __syncthreads();
    if (t4 == 0) {
#pragma unroll
        for (int h = 0; h < 2; h++) {
            const int row = wm * 16 + g + 8 * h;
            smred[wn * 64 + row * 2] = z2[h];
        }
    }
    __syncthreads();
    if (tid < 32) {
        float n2 = 0.f;
#pragma unroll
        for (int w = 0; w < 4; w++) n2 += smred[w * 64 + tid * 2];
        g_rnorm[((long)(row0 + tid) * 4 + md)] = 1.f / (sqrtf(n2) + 1e-6f);
    }
}

// ===========================================================================
// HEAD: bf16 hi/lo GEMM (round-13 config, control). CTA 64 rows x 128 cols,
// 3 CTAs/SM, grid (8, 128). Fused softmax/finalize.
// ===========================================================================
__global__ void __launch_bounds__(256, 3) head_bf16(
    const float* cls, float* out_logits, float* out_r,
    float* out_sim, float* out_contrib)
{
    constexpr int A_ARR   = 64 * 80;
    constexpr int B_ARR   = 128 * 80;
    constexpr int STAGE_B = 2 * A_ARR + 2 * B_ARR;   // 30720

    extern __shared__ char smem[];
    const uint32_t sbase = smem_u32(smem);
    const int tid = threadIdx.x, wid = tid >> 5, lane = tid & 31;

    const int row0 = blockIdx.y * 64;
    const __nv_bfloat16* Ah = g_Zhi + (long)row0 * DD;
    const __nv_bfloat16* Al = g_Zlo + (long)row0 * DD;
    const __nv_bfloat16* Bh = g_Bhi + (long)blockIdx.x * 128 * DD;
    const __nv_bfloat16* Bl = g_Blo + (long)blockIdx.x * 128 * DD;

    const int wm = wid >> 2, wn = wid & 3;
    const int g = lane >> 2, t4 = lane & 3;

    uint32_t aoff[2];
#pragma unroll
    for (int im = 0; im < 2; im++)
        aoff[im] = ((wm * 32 + im * 16 + (lane & 15)) * 40 + ((lane >> 4) << 3)) * 2;
    const uint32_t boff = ((wn * 32 + (lane & 7) + ((lane >> 4) << 3)) * 40
                           + (((lane >> 3) & 1) << 3)) * 2;

    float acc[2][4][4];
#pragma unroll
    for (int im = 0; im < 2; im++)
#pragma unroll
        for (int jn = 0; jn < 4; jn++)
#pragma unroll
            for (int q = 0; q < 4; q++) acc[im][jn][q] = 0.f;

    auto load_stage = [&](uint32_t tile_sm, int k0) {
#pragma unroll
        for (int i = 0; i < 2; i++) {   // A: 2 arrays x 256 uint4
            const int n = tid + (i << 8);
            const int a = n >> 8, idx = n & 255;
            const int row = idx >> 2, ch = idx & 3;
            const __nv_bfloat16* src = a ? Al : Ah;
            CP16(tile_sm + a * A_ARR + row * 80 + (ch << 4),
                 (const char*)(src + (long)row * DD + k0 + (ch << 3)));
        }
#pragma unroll
        for (int i = 0; i < 4; i++) {   // B: 2 arrays x 512 uint4
            const int m = tid + (i << 8);
            const int a = m >> 9, idx = m & 511;
            const int row = idx >> 2, ch = idx & 3;
            const __nv_bfloat16* src = a ? Bl : Bh;
            CP16(tile_sm + 2 * A_ARR + a * B_ARR + row * 80 + (ch << 4),
                 (const char*)(src + (long)row * DD + k0 + (ch << 3)));
        }
        CP_COMMIT();
    };

    load_stage(sbase + SM_T, 0);
    for (int kt = 0; kt < 8; kt++) {
        const bool hasNext = (kt + 1 < 8);
        if (hasNext) load_stage(sbase + SM_T + ((kt + 1) & 1) * STAGE_B, (kt + 1) << 5);
        if (hasNext) CP_WAIT1(); else CP_WAIT0();
        __syncthreads();

        const uint32_t sst = sbase + SM_T + (kt & 1) * STAGE_B;
#pragma unroll
        for (int ks = 0; ks < 64; ks += 32) {
            uint32_t ah[2][4], al[2][4];
#pragma unroll
            for (int im = 0; im < 2; im++) {
                LDM4(ah[im], sst + aoff[im] + ks);
                LDM4(al[im], sst + A_ARR + aoff[im] + ks);
            }
#pragma unroll
            for (int jj = 0; jj < 2; jj++) {
                uint32_t bh[4], bl[4];
                LDM4(bh, sst + 2 * A_ARR + boff + jj * 1280 + ks);
                LDM4(bl, sst + 2 * A_ARR + B_ARR + boff + jj * 1280 + ks);
#pragma unroll
                for (int im = 0; im < 2; im++) {
                    MMA_BF16(acc[im][2 * jj],     ah[im], &bh[0]);
                    MMA_BF16(acc[im][2 * jj],     ah[im], &bl[0]);
                    MMA_BF16(acc[im][2 * jj],     al[im], &bh[0]);
                    MMA_BF16(acc[im][2 * jj + 1], ah[im], &bh[2]);
                    MMA_BF16(acc[im][2 * jj + 1], ah[im], &bl[2]);
                    MMA_BF16(acc[im][2 * jj + 1], al[im], &bh[2]);
                }
            }
        }
        __syncthreads();
    }

    // fused softmax/finalize (softmax over m via shfl xor 4,8)
#pragma unroll
    for (int im = 0; im < 2; im++)
#pragma unroll
        for (int h = 0; h < 2; h++) {
            const long grow = row0 + wm * 32 + im * 16 + g + 8 * h;   // = b*4 + m
            const float rs = g_rnorm[grow] * INVTAU;
#pragma unroll
            for (int jn = 0; jn < 4; jn++) {
                const float s = acc[im][jn][h * 2] * rs;
                const float o = acc[im][jn][h * 2 + 1];
                float mx = s;
                mx = fmaxf(mx, __shfl_xor_sync(0xffffffffu, mx, 4));
                mx = fmaxf(mx, __shfl_xor_sync(0xffffffffu, mx, 8));
                const float e = __expf(s - mx);
                float tt = e + __shfl_xor_sync(0xffffffffu, e, 4);
                tt += __shfl_xor_sync(0xffffffffu, tt, 8);
                const float rr = e / tt;
                const float ct = o * rr;
                float lg = ct + __shfl_xor_sync(0xffffffffu, ct, 4);
                lg += __shfl_xor_sync(0xffffffffu, lg, 8);
                const int cg = blockIdx.x * 64 + wn * 16 + jn * 4 + t4;
                const long obase = grow * 512 + cg;
                out_sim[obase]     = s;
                out_r[obase]       = rr;
                out_contrib[obase] = ct;
                if ((grow & 3) == 0)
                    out_logits[(grow >> 2) * 512 + cg] = lg + __ldg(cls + cg);
            }
        }
}

// ---------------------------------------------------------------------------
// Bcat rows interleaved: row 2c = l2norm(U)_c, row 2c+1 = O_c  -> bf16 hi/lo
// ---------------------------------------------------------------------------
__global__ void __launch_bounds__(256) normcat_kernel(const float* __restrict__ U,
                                                      const float* __restrict__ O)
{
    const int rr = blockIdx.x, t = threadIdx.x;
    const int c = rr >> 1, kind = rr & 1;
    __shared__ float ws[8];
    float v;
    if (kind == 0) {
        float u = U[(long)c * DD + t];
        float q = u * u;
#pragma unroll
        for (int o = 16; o > 0; o >>= 1) q += __shfl_xor_sync(0xffffffffu, q, o);
        if ((t & 31) == 0) ws[t >> 5] = q;
        __syncthreads();
        float n2 = 0.f;
#pragma unroll
        for (int i = 0; i < 8; i++) n2 += ws[i];
        v = u / (sqrtf(n2) + 1e-6f);
    } else {
        v = O[(long)c * DD + t];
    }
    __nv_bfloat16 h, l; split2(v, h, l);
    g_Bhi[(long)rr * DD + t] = h;
    g_Blo[(long)rr * DD + t] = l;
}

// ---------------------------------------------------------------------------
extern "C" void kernel_launch(void* const* d_in, const int* in_sizes, int n_in,
                              void* d_out, int out_size)
{
    const float *f[4], *W[4], *bi[4], *ga[4], *be[4];
    if (in_sizes[1] == 256 * 1024) {   // dict order: (f,W,b,g,be) per modality
        for (int m = 0; m < 4; m++) {
            f[m]  = (const float*)d_in[m * 5 + 0];
            W[m]  = (const float*)d_in[m * 5 + 1];
            bi[m] = (const float*)d_in[m * 5 + 2];
            ga[m] = (const float*)d_in[m * 5 + 3];
            be[m] = (const float*)d_in[m * 5 + 4];
        }
    } else {                            // signature order
        for (int m = 0; m < 4; m++) f[m] = (const float*)d_in[m];
        for (int m = 0; m < 4; m++) {
            W[m]  = (const float*)d_in[4 + m * 4 + 0];
            bi[m] = (const float*)d_in[4 + m * 4 + 1];
            ga[m] = (const float*)d_in[4 + m * 4 + 2];
            be[m] = (const float*)d_in[4 + m * 4 + 3];
        }
    }
    const float* U   = (const float*)d_in[20];
    const float* O   = (const float*)d_in[21];
    const float* cls = (const float*)d_in[22];

    float* out         = (float*)d_out;
    float* out_logits  = out;
    float* out_r       = out + (long)BB * CC;
    float* out_sim     = out_r + (long)NROW * CC;
    float* out_contrib = out_sim + (long)NROW * CC;

    cudaFuncSetAttribute((const void*)proj_tf32,
                         cudaFuncAttributeMaxDynamicSharedMemorySize, SMEM_PROJ);
    cudaFuncSetAttribute((const void*)head_bf16,
                         cudaFuncAttributeMaxDynamicSharedMemorySize, SMEM_HEAD);

    normcat_kernel<<<1024, 256>>>(U, O);

    // projections + fused LayerNorm/l2 (tf32, consumes f/W fp32 directly)
    proj_tf32<<<dim3(1, 64, 4), 256, SMEM_PROJ>>>(
        f[0], f[1], f[2], f[3], W[0], W[1], W[2], W[3],
        bi[0], bi[1], bi[2], bi[3], ga[0], ga[1], ga[2], ga[3],
        be[0], be[1], be[2], be[3]);

    // head GEMM + fused softmax/finalize (bf16 hi/lo, round-13 control)
    head_bf16<<<dim3(8, 128, 1), 256, SMEM_HEAD>>>(
        cls, out_logits, out_r, out_sim, out_contrib);
}

// round 16
// speedup vs baseline: 1.4784x; 1.0641x over previous
#include <cuda_runtime.h>
#include <cuda_bf16.h>
#include <math.h>
#include <stdint.h>

#define BB 2048
#define DD 256
#define CC 512
#define NROW 8192
#define INVTAU (1.0f/0.07f)

// ---------------- scratch (no allocations allowed) ----------------
__device__ float g_Zf[NROW * DD];      // LN'd projections, fp32
__device__ float g_Bf[1024 * DD];      // interleaved rows: 2c=Un_c, 2c+1=O_c (fp32)
__device__ float g_rnorm[NROW];

#define MMA_TF32(d, a, b) asm volatile( \
    "mma.sync.aligned.m16n8k8.row.col.f32.tf32.tf32.f32 " \
    "{%0,%1,%2,%3}, {%4,%5,%6,%7}, {%8,%9}, {%0,%1,%2,%3};\n" \
    : "+f"((d)[0]), "+f"((d)[1]), "+f"((d)[2]), "+f"((d)[3]) \
    : "r"((a)[0]), "r"((a)[1]), "r"((a)[2]), "r"((a)[3]), "r"((b)[0]), "r"((b)[1]))

#define CVT_TF32(o, x) asm("cvt.rna.tf32.f32 %0, %1;" : "=r"(o) : "f"(x))

#define CP16(dst, src) asm volatile("cp.async.cg.shared.global [%0], [%1], 16;" :: "r"(dst), "l"(src))
#define CP_COMMIT()    asm volatile("cp.async.commit_group;" ::: "memory")
#define CP_WAIT0()     asm volatile("cp.async.wait_group 0;" ::: "memory")
#define CP_WAIT1()     asm volatile("cp.async.wait_group 1;" ::: "memory")

__device__ __forceinline__ uint32_t smem_u32(const void* p) {
    uint32_t a;
    asm("{ .reg .u64 t; cvta.to.shared.u64 t, %1; cvt.u32.u64 %0, t; }" : "=r"(a) : "l"(p));
    return a;
}

// common smem header
#define SM_PARAM 0
#define SM_RED   3072
#define SM_STAT  5120
#define SM_T     5632
// proj stage: A 32x144B + B 256x144B = 41472
#define PSTAGE   41472
#define SMEM_PROJ (SM_T + 2 * PSTAGE)    // 88576
// head stage: A 64x144B + B 128x144B = 27648
#define HSTAGE   27648
#define SMEM_HEAD (SM_T + 2 * HSTAGE)    // 60928 -> 3 CTAs/SM

// ===========================================================================
// PROJ: tf32 GEMM, CTA 32 rows x 256 cols, grid (1, 64, 4), 2 CTAs/SM.
// A = f (fp32), B = W (fp32). Fused LayerNorm + l2; Z emitted fp32.
// ===========================================================================
__global__ void __launch_bounds__(256, 2) proj_tf32(
    const float* fp0, const float* fp1, const float* fp2, const float* fp3,
    const float* W0, const float* W1, const float* W2, const float* W3,
    const float* b0, const float* b1, const float* b2, const float* b3,
    const float* G0, const float* G1, const float* G2, const float* G3,
    const float* e0, const float* e1, const float* e2, const float* e3)
{
    extern __shared__ char smem[];
    const uint32_t sbase = smem_u32(smem);
    const int tid = threadIdx.x, wid = tid >> 5, lane = tid & 31;
    float* smf   = (float*)(smem + SM_PARAM);
    float* smred = (float*)(smem + SM_RED);
    float* smst  = (float*)(smem + SM_STAT);

    const int md = blockIdx.z;
    {
        const float* bp = md == 0 ? b0 : md == 1 ? b1 : md == 2 ? b2 : b3;
        const float* gp = md == 0 ? G0 : md == 1 ? G1 : md == 2 ? G2 : G3;
        const float* ep = md == 0 ? e0 : md == 1 ? e1 : md == 2 ? e2 : e3;
        smf[tid] = bp[tid]; smf[256 + tid] = gp[tid]; smf[512 + tid] = ep[tid];
    }
    __syncthreads();

    const int Km[4] = {1024, 1024, 512, 256};
    const int K = Km[md];
    const float* F = md == 0 ? fp0 : md == 1 ? fp1 : md == 2 ? fp2 : fp3;
    const float* W = md == 0 ? W0 : md == 1 ? W1 : md == 2 ? W2 : W3;
    const int row0 = blockIdx.y * 32;
    const int nkt = K >> 5;

    const int wm = wid >> 2, wn = wid & 3;    // 2x4 warp grid, warp tile 16x64
    const int g = lane >> 2, t4 = lane & 3;

    float acc[8][4];
#pragma unroll
    for (int jn = 0; jn < 8; jn++)
#pragma unroll
        for (int q = 0; q < 4; q++) acc[jn][q] = 0.f;

    auto load_stage = [&](uint32_t tile_sm, int k0) {
        {
            const int row = tid >> 3, ch = tid & 7;   // A: 256 uint4
            CP16(tile_sm + row * 144 + (ch << 4),
                 (const char*)(F + (long)(row0 + row) * K + k0 + (ch << 2)));
        }
#pragma unroll
        for (int i = 0; i < 8; i++) {                 // B: 2048 uint4
            const int m = tid + (i << 8);
            const int row = m >> 3, ch = m & 7;
            CP16(tile_sm + 4608 + row * 144 + (ch << 4),
                 (const char*)(W + (long)row * K + k0 + (ch << 2)));
        }
        CP_COMMIT();
    };

    load_stage(sbase + SM_T, 0);
    for (int kt = 0; kt < nkt; kt++) {
        const bool hasNext = (kt + 1 < nkt);
        if (hasNext) load_stage(sbase + SM_T + ((kt + 1) & 1) * PSTAGE, (kt + 1) << 5);
        if (hasNext) CP_WAIT1(); else CP_WAIT0();
        __syncthreads();

        const float* smA = (const float*)(smem + SM_T + (kt & 1) * PSTAGE);
        const float* smB = smA + 1152;
        const float* A0 = smA + (wm * 16 + g) * 36 + t4;
#pragma unroll
        for (int s = 0; s < 4; s++) {
            uint32_t a[4];
            CVT_TF32(a[0], A0[s * 8]);
            CVT_TF32(a[1], A0[8 * 36 + s * 8]);
            CVT_TF32(a[2], A0[s * 8 + 4]);
            CVT_TF32(a[3], A0[8 * 36 + s * 8 + 4]);
#pragma unroll
            for (int jn = 0; jn < 8; jn++) {
                const int n = wn * 64 + jn * 8 + g;
                uint32_t b[2];
                CVT_TF32(b[0], smB[n * 36 + s * 8 + t4]);
                CVT_TF32(b[1], smB[n * 36 + s * 8 + t4 + 4]);
                MMA_TF32(acc[jn], a, b);
            }
        }
        __syncthreads();
    }

    // ---- fused LayerNorm + l2 epilogue
    float sums[2] = {0.f, 0.f}, ssqs[2] = {0.f, 0.f};
#pragma unroll
    for (int jn = 0; jn < 8; jn++)
#pragma unroll
        for (int h = 0; h < 2; h++)
#pragma unroll
            for (int e = 0; e < 2; e++) {
                const int col = wn * 64 + jn * 8 + 2 * t4 + e;
                const float y = acc[jn][h * 2 + e] + smf[col];
                acc[jn][h * 2 + e] = y;
                sums[h] += y; ssqs[h] += y * y;
            }
#pragma unroll
    for (int h = 0; h < 2; h++) {
        sums[h] += __shfl_xor_sync(0xffffffffu, sums[h], 1);
        sums[h] += __shfl_xor_sync(0xffffffffu, sums[h], 2);
        ssqs[h] += __shfl_xor_sync(0xffffffffu, ssqs[h], 1);
        ssqs[h] += __shfl_xor_sync(0xffffffffu, ssqs[h], 2);
    }
    if (t4 == 0) {
#pragma unroll
        for (int h = 0; h < 2; h++) {
            const int row = wm * 16 + g + 8 * h;
            smred[wn * 64 + row * 2]     = sums[h];
            smred[wn * 64 + row * 2 + 1] = ssqs[h];
        }
    }
    __syncthreads();
    if (tid < 32) {
        float s = 0.f, q = 0.f;
#pragma unroll
        for (int w = 0; w < 4; w++) {
            s += smred[w * 64 + tid * 2];
            q += smred[w * 64 + tid * 2 + 1];
        }
        const float mu = s * (1.f / 256.f);
        const float var = q * (1.f / 256.f) - mu * mu;
        smst[tid * 2]     = mu;
        smst[tid * 2 + 1] = rsqrtf(var + 1e-5f);
    }
    __syncthreads();

    float z2[2] = {0.f, 0.f};
#pragma unroll
    for (int h = 0; h < 2; h++) {
        const int row = wm * 16 + g + 8 * h;
        const float mu = smst[row * 2], rstd = smst[row * 2 + 1];
        const long zrow = ((long)(row0 + row) * 4 + md) * 256;
#pragma unroll
        for (int jn = 0; jn < 8; jn++) {
            const int c0 = wn * 64 + jn * 8 + 2 * t4;
            const float z0 = (acc[jn][h * 2]     - mu) * rstd * smf[256 + c0]     + smf[512 + c0];
            const float z1 = (acc[jn][h * 2 + 1] - mu) * rstd * smf[256 + c0 + 1] + smf[512 + c0 + 1];
            z2[h] += z0 * z0 + z1 * z1;
            *(float2*)(g_Zf + zrow + c0) = make_float2(z0, z1);
        }
    }
#pragma unroll
    for (int h = 0; h < 2; h++) {
        z2[h] += __shfl_xor_sync(0xffffffffu, z2[h], 1);
        z2[h] += __shfl_xor_sync(0xffffffffu, z2[h], 2);
    }
    __syncthreads();
    if (t4 == 0) {
#pragma unroll
        for (int h = 0; h < 2; h++) {
            const int row = wm * 16 + g + 8 * h;
            smred[wn * 64 + row * 2] = z2[h];
        }
    }
    __syncthreads();
    if (tid < 32) {
        float n2 = 0.f;
#pragma unroll
        for (int w = 0; w < 4; w++) n2 += smred[w * 64 + tid * 2];
        g_rnorm[((long)(row0 + tid) * 4 + md)] = 1.f / (sqrtf(n2) + 1e-6f);
    }
}

// ===========================================================================
// HEAD: tf32 GEMM, CTA 64 rows x 128 cols, grid (8, 128), 3 CTAs/SM.
// A = Z (fp32), B = Bcat (fp32). Fused softmax/finalize.
// ===========================================================================
__global__ void __launch_bounds__(256, 3) head_tf32(
    const float* cls, float* out_logits, float* out_r,
    float* out_sim, float* out_contrib)
{
    extern __shared__ char smem[];
    const uint32_t sbase = smem_u32(smem);
    const int tid = threadIdx.x, wid = tid >> 5, lane = tid & 31;

    const int row0 = blockIdx.y * 64;
    const float* A = g_Zf + (long)row0 * DD;
    const float* B = g_Bf + (long)blockIdx.x * 128 * DD;

    const int wm = wid >> 2, wn = wid & 3;   // warp tile 32x32
    const int g = lane >> 2, t4 = lane & 3;

    float acc[2][4][4];
#pragma unroll
    for (int im = 0; im < 2; im++)
#pragma unroll
        for (int jn = 0; jn < 4; jn++)
#pragma unroll
            for (int q = 0; q < 4; q++) acc[im][jn][q] = 0.f;

    auto load_stage = [&](uint32_t tile_sm, int k0) {
#pragma unroll
        for (int i = 0; i < 2; i++) {   // A: 512 uint4
            const int m = tid + (i << 8);
            const int row = m >> 3, ch = m & 7;
            CP16(tile_sm + row * 144 + (ch << 4),
                 (const char*)(A + (long)row * DD + k0 + (ch << 2)));
        }
#pragma unroll
        for (int i = 0; i < 4; i++) {   // B: 1024 uint4
            const int m = tid + (i << 8);
            const int row = m >> 3, ch = m & 7;
            CP16(tile_sm + 9216 + row * 144 + (ch << 4),
                 (const char*)(B + (long)row * DD + k0 + (ch << 2)));
        }
        CP_COMMIT();
    };

    load_stage(sbase + SM_T, 0);
    for (int kt = 0; kt < 8; kt++) {
        const bool hasNext = (kt + 1 < 8);
        if (hasNext) load_stage(sbase + SM_T + ((kt + 1) & 1) * HSTAGE, (kt + 1) << 5);
        if (hasNext) CP_WAIT1(); else CP_WAIT0();
        __syncthreads();

        const float* smA = (const float*)(smem + SM_T + (kt & 1) * HSTAGE);
        const float* smB = smA + 2304;   // 64*36 floats
        const float* A0[2];
#pragma unroll
        for (int im = 0; im < 2; im++)
            A0[im] = smA + (wm * 32 + im * 16 + g) * 36 + t4;
#pragma unroll
        for (int s = 0; s < 4; s++) {
            uint32_t a[2][4];
#pragma unroll
            for (int im = 0; im < 2; im++) {
                CVT_TF32(a[im][0], A0[im][s * 8]);
                CVT_TF32(a[im][1], A0[im][8 * 36 + s * 8]);
                CVT_TF32(a[im][2], A0[im][s * 8 + 4]);
                CVT_TF32(a[im][3], A0[im][8 * 36 + s * 8 + 4]);
            }
#pragma unroll
            for (int jn = 0; jn < 4; jn++) {
                const int n = wn * 32 + jn * 8 + g;
                uint32_t b[2];
                CVT_TF32(b[0], smB[n * 36 + s * 8 + t4]);
                CVT_TF32(b[1], smB[n * 36 + s * 8 + t4 + 4]);
#pragma unroll
                for (int im = 0; im < 2; im++)
                    MMA_TF32(acc[im][jn], a[im], b);
            }
        }
        __syncthreads();
    }

    // fused softmax/finalize (softmax over m via shfl xor 4,8)
#pragma unroll
    for (int im = 0; im < 2; im++)
#pragma unroll
        for (int h = 0; h < 2; h++) {
            const long grow = row0 + wm * 32 + im * 16 + g + 8 * h;   // = b*4 + m
            const float rs = g_rnorm[grow] * INVTAU;
#pragma unroll
            for (int jn = 0; jn < 4; jn++) {
                const float s = acc[im][jn][h * 2] * rs;
                const float o = acc[im][jn][h * 2 + 1];
                float mx = s;
                mx = fmaxf(mx, __shfl_xor_sync(0xffffffffu, mx, 4));
                mx = fmaxf(mx, __shfl_xor_sync(0xffffffffu, mx, 8));
                const float e = __expf(s - mx);
                float tt = e + __shfl_xor_sync(0xffffffffu, e, 4);
                tt += __shfl_xor_sync(0xffffffffu, tt, 8);
                const float rr = e / tt;
                const float ct = o * rr;
                float lg = ct + __shfl_xor_sync(0xffffffffu, ct, 4);
                lg += __shfl_xor_sync(0xffffffffu, lg, 8);
                const int cg = blockIdx.x * 64 + wn * 16 + jn * 4 + t4;
                const long obase = grow * 512 + cg;
                out_sim[obase]     = s;
                out_r[obase]       = rr;
                out_contrib[obase] = ct;
                if ((grow & 3) == 0)
                    out_logits[(grow >> 2) * 512 + cg] = lg + __ldg(cls + cg);
            }
        }
}

// ---------------------------------------------------------------------------
// Bcat rows interleaved fp32: row 2c = l2norm(U)_c, row 2c+1 = O_c
// ---------------------------------------------------------------------------
__global__ void __launch_bounds__(256) normcat_kernel(const float* __restrict__ U,
                                                      const float* __restrict__ O)
{
    const int rr = blockIdx.x, t = threadIdx.x;
    const int c = rr >> 1, kind = rr & 1;
    __shared__ float ws[8];
    float v;
    if (kind == 0) {
        float u = U[(long)c * DD + t];
        float q = u * u;
#pragma unroll
        for (int o = 16; o > 0; o >>= 1) q += __shfl_xor_sync(0xffffffffu, q, o);
        if ((t & 31) == 0) ws[t >> 5] = q;
        __syncthreads();
        float n2 = 0.f;
#pragma unroll
        for (int i = 0; i < 8; i++) n2 += ws[i];
        v = u / (sqrtf(n2) + 1e-6f);
    } else {
        v = O[(long)c * DD + t];
    }
    g_Bf[(long)rr * DD + t] = v;
}

// ---------------------------------------------------------------------------
extern "C" void kernel_launch(void* const* d_in, const int* in_sizes, int n_in,
                              void* d_out, int out_size)
{
    const float *f[4], *W[4], *bi[4], *ga[4], *be[4];
    if (in_sizes[1] == 256 * 1024) {   // dict order: (f,W,b,g,be) per modality
        for (int m = 0; m < 4; m++) {
            f[m]  = (const float*)d_in[m * 5 + 0];
            W[m]  = (const float*)d_in[m * 5 + 1];
            bi[m] = (const float*)d_in[m * 5 + 2];
            ga[m] = (const float*)d_in[m * 5 + 3];
            be[m] = (const float*)d_in[m * 5 + 4];
        }
    } else {                            // signature order
        for (int m = 0; m < 4; m++) f[m] = (const float*)d_in[m];
        for (int m = 0; m < 4; m++) {
            W[m]  = (const float*)d_in[4 + m * 4 + 0];
            bi[m] = (const float*)d_in[4 + m * 4 + 1];
            ga[m] = (const float*)d_in[4 + m * 4 + 2];
            be[m] = (const float*)d_in[4 + m * 4 + 3];
        }
    }
    const float* U   = (const float*)d_in[20];
    const float* O   = (const float*)d_in[21];
    const float* cls = (const float*)d_in[22];

    float* out         = (float*)d_out;
    float* out_logits  = out;
    float* out_r       = out + (long)BB * CC;
    float* out_sim     = out_r + (long)NROW * CC;
    float* out_contrib = out_sim + (long)NROW * CC;

    cudaFuncSetAttribute((const void*)proj_tf32,
                         cudaFuncAttributeMaxDynamicSharedMemorySize, SMEM_PROJ);
    cudaFuncSetAttribute((const void*)head_tf32,
                         cudaFuncAttributeMaxDynamicSharedMemorySize, SMEM_HEAD);

    normcat_kernel<<<1024, 256>>>(U, O);

    // projections + fused LayerNorm/l2 (tf32, consumes f/W fp32 directly)
    proj_tf32<<<dim3(1, 64, 4), 256, SMEM_PROJ>>>(
        f[0], f[1], f[2], f[3], W[0], W[1], W[2], W[3],
        bi[0], bi[1], bi[2], bi[3], ga[0], ga[1], ga[2], ga[3],
        be[0], be[1], be[2], be[3]);

    // head GEMM + fused softmax/finalize (tf32)
    head_tf32<<<dim3(8, 128, 1), 256, SMEM_HEAD>>>(
        cls, out_logits, out_r, out_sim, out_contrib);
}

// round 17
// speedup vs baseline: 1.4789x; 1.0003x over previous
#include <cuda_runtime.h>
#include <cuda_bf16.h>
#include <math.h>
#include <stdint.h>

#define BB 2048
#define DD 256
#define CC 512
#define NROW 8192
#define INVTAU (1.0f/0.07f)

// ---------------- scratch (no allocations allowed) ----------------
__device__ float g_Zf[NROW * DD];      // LN'd projections, pre-rounded to tf32
__device__ float g_Bf[1024 * DD];      // interleaved rows: 2c=Un_c, 2c+1=O_c (tf32)
__device__ float g_rnorm[NROW];

#define MMA_TF32(d, a, b) asm volatile( \
    "mma.sync.aligned.m16n8k8.row.col.f32.tf32.tf32.f32 " \
    "{%0,%1,%2,%3}, {%4,%5,%6,%7}, {%8,%9}, {%0,%1,%2,%3};\n" \
    : "+f"((d)[0]), "+f"((d)[1]), "+f"((d)[2]), "+f"((d)[3]) \
    : "r"((a)[0]), "r"((a)[1]), "r"((a)[2]), "r"((a)[3]), "r"((b)[0]), "r"((b)[1]))

#define CVT_TF32(o, x) asm("cvt.rna.tf32.f32 %0, %1;" : "=r"(o) : "f"(x))

__device__ __forceinline__ float tf32r(float x) {
    uint32_t u; CVT_TF32(u, x);
    return __uint_as_float(u);
}

#define CP16(dst, src) asm volatile("cp.async.cg.shared.global [%0], [%1], 16;" :: "r"(dst), "l"(src))
#define CP_COMMIT()    asm volatile("cp.async.commit_group;" ::: "memory")
#define CP_WAIT0()     asm volatile("cp.async.wait_group 0;" ::: "memory")
#define CP_WAIT1()     asm volatile("cp.async.wait_group 1;" ::: "memory")

__device__ __forceinline__ uint32_t smem_u32(const void* p) {
    uint32_t a;
    asm("{ .reg .u64 t; cvta.to.shared.u64 t, %1; cvt.u32.u64 %0, t; }" : "=r"(a) : "l"(p));
    return a;
}

// common smem header
#define SM_PARAM 0
#define SM_RED   3072
#define SM_STAT  5120
#define SM_T     5632
// proj stage: A 32x144B + B 256x144B = 41472
#define PSTAGE   41472
#define SMEM_PROJ (SM_T + 2 * PSTAGE)    // 88576
// head stage: A 64x144B + B 128x144B = 27648
#define HSTAGE   27648
#define SMEM_HEAD (SM_T + 2 * HSTAGE)    // 60928 -> 3 CTAs/SM

// ===========================================================================
// PROJ: tf32 GEMM, CTA 32 rows x 256 cols, grid (1, 64, 4), 2 CTAs/SM.
// A = f (fp32), B = W (fp32). Fused LayerNorm + l2; Z emitted tf32-rounded.
// ===========================================================================
__global__ void __launch_bounds__(256, 2) proj_tf32(
    const float* fp0, const float* fp1, const float* fp2, const float* fp3,
    const float* W0, const float* W1, const float* W2, const float* W3,
    const float* b0, const float* b1, const float* b2, const float* b3,
    const float* G0, const float* G1, const float* G2, const float* G3,
    const float* e0, const float* e1, const float* e2, const float* e3)
{
    extern __shared__ char smem[];
    const uint32_t sbase = smem_u32(smem);
    const int tid = threadIdx.x, wid = tid >> 5, lane = tid & 31;
    float* smf   = (float*)(smem + SM_PARAM);
    float* smred = (float*)(smem + SM_RED);
    float* smst  = (float*)(smem + SM_STAT);

    const int md = blockIdx.z;
    {
        const float* bp = md == 0 ? b0 : md == 1 ? b1 : md == 2 ? b2 : b3;
        const float* gp = md == 0 ? G0 : md == 1 ? G1 : md == 2 ? G2 : G3;
        const float* ep = md == 0 ? e0 : md == 1 ? e1 : md == 2 ? e2 : e3;
        smf[tid] = bp[tid]; smf[256 + tid] = gp[tid]; smf[512 + tid] = ep[tid];
    }
    __syncthreads();

    const int Km[4] = {1024, 1024, 512, 256};
    const int K = Km[md];
    const float* F = md == 0 ? fp0 : md == 1 ? fp1 : md == 2 ? fp2 : fp3;
    const float* W = md == 0 ? W0 : md == 1 ? W1 : md == 2 ? W2 : W3;
    const int row0 = blockIdx.y * 32;
    const int nkt = K >> 5;

    const int wm = wid >> 2, wn = wid & 3;    // 2x4 warp grid, warp tile 16x64
    const int g = lane >> 2, t4 = lane & 3;

    float acc[8][4];
#pragma unroll
    for (int jn = 0; jn < 8; jn++)
#pragma unroll
        for (int q = 0; q < 4; q++) acc[jn][q] = 0.f;

    auto load_stage = [&](uint32_t tile_sm, int k0) {
        {
            const int row = tid >> 3, ch = tid & 7;   // A: 256 uint4
            CP16(tile_sm + row * 144 + (ch << 4),
                 (const char*)(F + (long)(row0 + row) * K + k0 + (ch << 2)));
        }
#pragma unroll
        for (int i = 0; i < 8; i++) {                 // B: 2048 uint4
            const int m = tid + (i << 8);
            const int row = m >> 3, ch = m & 7;
            CP16(tile_sm + 4608 + row * 144 + (ch << 4),
                 (const char*)(W + (long)row * K + k0 + (ch << 2)));
        }
        CP_COMMIT();
    };

    load_stage(sbase + SM_T, 0);
    for (int kt = 0; kt < nkt; kt++) {
        const bool hasNext = (kt + 1 < nkt);
        if (hasNext) load_stage(sbase + SM_T + ((kt + 1) & 1) * PSTAGE, (kt + 1) << 5);
        if (hasNext) CP_WAIT1(); else CP_WAIT0();
        __syncthreads();

        const float* smA = (const float*)(smem + SM_T + (kt & 1) * PSTAGE);
        const float* smB = smA + 1152;
        const float* A0 = smA + (wm * 16 + g) * 36 + t4;
#pragma unroll
        for (int s = 0; s < 4; s++) {
            uint32_t a[4];
            CVT_TF32(a[0], A0[s * 8]);
            CVT_TF32(a[1], A0[8 * 36 + s * 8]);
            CVT_TF32(a[2], A0[s * 8 + 4]);
            CVT_TF32(a[3], A0[8 * 36 + s * 8 + 4]);
#pragma unroll
            for (int jn = 0; jn < 8; jn++) {
                const int n = wn * 64 + jn * 8 + g;
                uint32_t b[2];
                CVT_TF32(b[0], smB[n * 36 + s * 8 + t4]);
                CVT_TF32(b[1], smB[n * 36 + s * 8 + t4 + 4]);
                MMA_TF32(acc[jn], a, b);
            }
        }
        __syncthreads();
    }

    // ---- fused LayerNorm + l2 epilogue
    float sums[2] = {0.f, 0.f}, ssqs[2] = {0.f, 0.f};
#pragma unroll
    for (int jn = 0; jn < 8; jn++)
#pragma unroll
        for (int h = 0; h < 2; h++)
#pragma unroll
            for (int e = 0; e < 2; e++) {
                const int col = wn * 64 + jn * 8 + 2 * t4 + e;
                const float y = acc[jn][h * 2 + e] + smf[col];
                acc[jn][h * 2 + e] = y;
                sums[h] += y; ssqs[h] += y * y;
            }
#pragma unroll
    for (int h = 0; h < 2; h++) {
        sums[h] += __shfl_xor_sync(0xffffffffu, sums[h], 1);
        sums[h] += __shfl_xor_sync(0xffffffffu, sums[h], 2);
        ssqs[h] += __shfl_xor_sync(0xffffffffu, ssqs[h], 1);
        ssqs[h] += __shfl_xor_sync(0xffffffffu, ssqs[h], 2);
    }
    if (t4 == 0) {
#pragma unroll
        for (int h = 0; h < 2; h++) {
            const int row = wm * 16 + g + 8 * h;
            smred[wn * 64 + row * 2]     = sums[h];
            smred[wn * 64 + row * 2 + 1] = ssqs[h];
        }
    }
    __syncthreads();
    if (tid < 32) {
        float s = 0.f, q = 0.f;
#pragma unroll
        for (int w = 0; w < 4; w++) {
            s += smred[w * 64 + tid * 2];
            q += smred[w * 64 + tid * 2 + 1];
        }
        const float mu = s * (1.f / 256.f);
        const float var = q * (1.f / 256.f) - mu * mu;
        smst[tid * 2]     = mu;
        smst[tid * 2 + 1] = rsqrtf(var + 1e-5f);
    }
    __syncthreads();

    float z2[2] = {0.f, 0.f};
#pragma unroll
    for (int h = 0; h < 2; h++) {
        const int row = wm * 16 + g + 8 * h;
        const float mu = smst[row * 2], rstd = smst[row * 2 + 1];
        const long zrow = ((long)(row0 + row) * 4 + md) * 256;
#pragma unroll
        for (int jn = 0; jn < 8; jn++) {
            const int c0 = wn * 64 + jn * 8 + 2 * t4;
            const float z0 = (acc[jn][h * 2]     - mu) * rstd * smf[256 + c0]     + smf[512 + c0];
            const float z1 = (acc[jn][h * 2 + 1] - mu) * rstd * smf[256 + c0 + 1] + smf[512 + c0 + 1];
            z2[h] += z0 * z0 + z1 * z1;   // rnorm from full-precision z (as before)
            // store tf32-rounded z: identical value the head's in-loop CVT made
            *(float2*)(g_Zf + zrow + c0) = make_float2(tf32r(z0), tf32r(z1));
        }
    }
#pragma unroll
    for (int h = 0; h < 2; h++) {
        z2[h] += __shfl_xor_sync(0xffffffffu, z2[h], 1);
        z2[h] += __shfl_xor_sync(0xffffffffu, z2[h], 2);
    }
    __syncthreads();
    if (t4 == 0) {
#pragma unroll
        for (int h = 0; h < 2; h++) {
            const int row = wm * 16 + g + 8 * h;
            smred[wn * 64 + row * 2] = z2[h];
        }
    }
    __syncthreads();
    if (tid < 32) {
        float n2 = 0.f;
#pragma unroll
        for (int w = 0; w < 4; w++) n2 += smred[w * 64 + tid * 2];
        g_rnorm[((long)(row0 + tid) * 4 + md)] = 1.f / (sqrtf(n2) + 1e-6f);
    }
}

// ===========================================================================
// HEAD: tf32 GEMM, CTA 64 rows x 128 cols, grid (8, 128), 3 CTAs/SM.
// A/B pre-rounded tf32 in gmem -> NO cvt in the mainloop.
// ===========================================================================
__global__ void __launch_bounds__(256, 3) head_tf32(
    const float* cls, float* out_logits, float* out_r,
    float* out_sim, float* out_contrib)
{
    extern __shared__ char smem[];
    const uint32_t sbase = smem_u32(smem);
    const int tid = threadIdx.x, wid = tid >> 5, lane = tid & 31;

    const int row0 = blockIdx.y * 64;
    const float* A = g_Zf + (long)row0 * DD;
    const float* B = g_Bf + (long)blockIdx.x * 128 * DD;

    const int wm = wid >> 2, wn = wid & 3;   // warp tile 32x32
    const int g = lane >> 2, t4 = lane & 3;

    float acc[2][4][4];
#pragma unroll
    for (int im = 0; im < 2; im++)
#pragma unroll
        for (int jn = 0; jn < 4; jn++)
#pragma unroll
            for (int q = 0; q < 4; q++) acc[im][jn][q] = 0.f;

    auto load_stage = [&](uint32_t tile_sm, int k0) {
#pragma unroll
        for (int i = 0; i < 2; i++) {   // A: 512 uint4
            const int m = tid + (i << 8);
            const int row = m >> 3, ch = m & 7;
            CP16(tile_sm + row * 144 + (ch << 4),
                 (const char*)(A + (long)row * DD + k0 + (ch << 2)));
        }
#pragma unroll
        for (int i = 0; i < 4; i++) {   // B: 1024 uint4
            const int m = tid + (i << 8);
            const int row = m >> 3, ch = m & 7;
            CP16(tile_sm + 9216 + row * 144 + (ch << 4),
                 (const char*)(B + (long)row * DD + k0 + (ch << 2)));
        }
        CP_COMMIT();
    };

    load_stage(sbase + SM_T, 0);
    for (int kt = 0; kt < 8; kt++) {
        const bool hasNext = (kt + 1 < 8);
        if (hasNext) load_stage(sbase + SM_T + ((kt + 1) & 1) * HSTAGE, (kt + 1) << 5);
        if (hasNext) CP_WAIT1(); else CP_WAIT0();
        __syncthreads();

        const float* smA = (const float*)(smem + SM_T + (kt & 1) * HSTAGE);
        const float* smB = smA + 2304;   // 64*36 floats
        const float* A0[2];
#pragma unroll
        for (int im = 0; im < 2; im++)
            A0[im] = smA + (wm * 32 + im * 16 + g) * 36 + t4;
#pragma unroll
        for (int s = 0; s < 4; s++) {
            uint32_t a[2][4];
#pragma unroll
            for (int im = 0; im < 2; im++) {
                a[im][0] = __float_as_uint(A0[im][s * 8]);
                a[im][1] = __float_as_uint(A0[im][8 * 36 + s * 8]);
                a[im][2] = __float_as_uint(A0[im][s * 8 + 4]);
                a[im][3] = __float_as_uint(A0[im][8 * 36 + s * 8 + 4]);
            }
#pragma unroll
            for (int jn = 0; jn < 4; jn++) {
                const int n = wn * 32 + jn * 8 + g;
                uint32_t b[2];
                b[0] = __float_as_uint(smB[n * 36 + s * 8 + t4]);
                b[1] = __float_as_uint(smB[n * 36 + s * 8 + t4 + 4]);
#pragma unroll
                for (int im = 0; im < 2; im++)
                    MMA_TF32(acc[im][jn], a[im], b);
            }
        }
        __syncthreads();
    }

    // fused softmax/finalize (softmax over m via shfl xor 4,8)
#pragma unroll
    for (int im = 0; im < 2; im++)
#pragma unroll
        for (int h = 0; h < 2; h++) {
            const long grow = row0 + wm * 32 + im * 16 + g + 8 * h;   // = b*4 + m
            const float rs = g_rnorm[grow] * INVTAU;
#pragma unroll
            for (int jn = 0; jn < 4; jn++) {
                const float s = acc[im][jn][h * 2] * rs;
                const float o = acc[im][jn][h * 2 + 1];
                float mx = s;
                mx = fmaxf(mx, __shfl_xor_sync(0xffffffffu, mx, 4));
                mx = fmaxf(mx, __shfl_xor_sync(0xffffffffu, mx, 8));
                const float e = __expf(s - mx);
                float tt = e + __shfl_xor_sync(0xffffffffu, e, 4);
                tt += __shfl_xor_sync(0xffffffffu, tt, 8);
                const float rr = e / tt;
                const float ct = o * rr;
                float lg = ct + __shfl_xor_sync(0xffffffffu, ct, 4);
                lg += __shfl_xor_sync(0xffffffffu, lg, 8);
                const int cg = blockIdx.x * 64 + wn * 16 + jn * 4 + t4;
                const long obase = grow * 512 + cg;
                out_sim[obase]     = s;
                out_r[obase]       = rr;
                out_contrib[obase] = ct;
                if ((grow & 3) == 0)
                    out_logits[(grow >> 2) * 512 + cg] = lg + __ldg(cls + cg);
            }
        }
}

// ---------------------------------------------------------------------------
// Bcat rows interleaved, tf32-rounded: row 2c = l2norm(U)_c, row 2c+1 = O_c
// ---------------------------------------------------------------------------
__global__ void __launch_bounds__(256) normcat_kernel(const float* __restrict__ U,
                                                      const float* __restrict__ O)
{
    const int rr = blockIdx.x, t = threadIdx.x;
    const int c = rr >> 1, kind = rr & 1;
    __shared__ float ws[8];
    float v;
    if (kind == 0) {
        float u = U[(long)c * DD + t];
        float q = u * u;
#pragma unroll
        for (int o = 16; o > 0; o >>= 1) q += __shfl_xor_sync(0xffffffffu, q, o);
        if ((t & 31) == 0) ws[t >> 5] = q;
        __syncthreads();
        float n2 = 0.f;
#pragma unroll
        for (int i = 0; i < 8; i++) n2 += ws[i];
        v = u / (sqrtf(n2) + 1e-6f);
    } else {
        v = O[(long)c * DD + t];
    }
    g_Bf[(long)rr * DD + t] = tf32r(v);
}

// ---------------------------------------------------------------------------
extern "C" void kernel_launch(void* const* d_in, const int* in_sizes, int n_in,
                              void* d_out, int out_size)
{
    const float *f[4], *W[4], *bi[4], *ga[4], *be[4];
    if (in_sizes[1] == 256 * 1024) {   // dict order: (f,W,b,g,be) per modality
        for (int m = 0; m < 4; m++) {
            f[m]  = (const float*)d_in[m * 5 + 0];
            W[m]  = (const float*)d_in[m * 5 + 1];
            bi[m] = (const float*)d_in[m * 5 + 2];
            ga[m] = (const float*)d_in[m * 5 + 3];
            be[m] = (const float*)d_in[m * 5 + 4];
        }
    } else {                            // signature order
        for (int m = 0; m < 4; m++) f[m] = (const float*)d_in[m];
        for (int m = 0; m < 4; m++) {
            W[m]  = (const float*)d_in[4 + m * 4 + 0];
            bi[m] = (const float*)d_in[4 + m * 4 + 1];
            ga[m] = (const float*)d_in[4 + m * 4 + 2];
            be[m] = (const float*)d_in[4 + m * 4 + 3];
        }
    }
    const float* U   = (const float*)d_in[20];
    const float* O   = (const float*)d_in[21];
    const float* cls = (const float*)d_in[22];

    float* out         = (float*)d_out;
    float* out_logits  = out;
    float* out_r       = out + (long)BB * CC;
    float* out_sim     = out_r + (long)NROW * CC;
    float* out_contrib = out_sim + (long)NROW * CC;

    cudaFuncSetAttribute((const void*)proj_tf32,
                         cudaFuncAttributeMaxDynamicSharedMemorySize, SMEM_PROJ);
    cudaFuncSetAttribute((const void*)head_tf32,
                         cudaFuncAttributeMaxDynamicSharedMemorySize, SMEM_HEAD);

    normcat_kernel<<<1024, 256>>>(U, O);

    // projections + fused LayerNorm/l2 (tf32, consumes f/W fp32 directly)
    proj_tf32<<<dim3(1, 64, 4), 256, SMEM_PROJ>>>(
        f[0], f[1], f[2], f[3], W[0], W[1], W[2], W[3],
        bi[0], bi[1], bi[2], bi[3], ga[0], ga[1], ga[2], ga[3],
        be[0], be[1], be[2], be[3]);

    // head GEMM + fused softmax/finalize (tf32, no in-loop cvt)
    head_tf32<<<dim3(8, 128, 1), 256, SMEM_HEAD>>>(
        cls, out_logits, out_r, out_sim, out_contrib);
}